// round 4
// baseline (speedup 1.0000x reference)
#include <cuda_runtime.h>
#include <cuda_fp16.h>

#define N_NODES 100000
#define N_EDGES 3200000
#define IN_DIM 128
#define HID 64
#define OUT_DIM 32
#define N_LAYERS 3

#define NBLK ((N_NODES + 255) / 256)   // 391 scan blocks

// Scratch: device globals (alloc-free, graph-capture safe; zero-init at load)
__device__ float  g_hA[N_NODES * HID];
__device__ float  g_hB[N_NODES * HID];
__device__ float  g_hsum[N_NODES * HID];
__device__ __half g_hHalf[N_NODES * HID];   // fp16 copy of current h for gather
__device__ int2   g_es[N_EDGES];            // {src, weight_bits} grouped by dst
__device__ int    g_cnt[N_NODES];           // left zeroed at end of every call
__device__ int    g_rowptr[N_NODES + 1];
__device__ int    g_ofs[N_NODES];
__device__ int    g_bsum[NBLK];
__device__ int    g_boff[NBLK];

// ---------------------------------------------------------------------------
// Per-warp dtype detect: int64 elements (values < 2^31) have zero odd words.
// int32 random node ids: 32 consecutive odd words all zero w.p. ~(1e-5)^32.
// Requires full warps (N_EDGES % 32 == 0).
// ---------------------------------------------------------------------------
__device__ __forceinline__ bool warp_is64(const int* ei32, int i) {
    return __all_sync(0xffffffffu, ei32[2 * i + 1] == 0);
}

// ---------------------------------------------------------------------------
// Histogram of dst (fused dtype detect). g_cnt must enter zeroed.
// ---------------------------------------------------------------------------
__global__ void hist_kernel(const void* __restrict__ ei) {
    int i = blockIdx.x * blockDim.x + threadIdx.x;
    if (i >= N_EDGES) return;
    bool is64 = warp_is64((const int*)ei, i);
    int dst = is64 ? (int)((const long long*)ei)[(long long)N_EDGES + i]
                   : ((const int*)ei)[N_EDGES + i];
    atomicAdd(&g_cnt[dst], 1);
}

// ---------------------------------------------------------------------------
// 3-phase exclusive scan of g_cnt -> g_rowptr / g_ofs
// ---------------------------------------------------------------------------
__global__ void scan1_kernel() {   // per-block reduce
    __shared__ int s[256];
    int i = blockIdx.x * 256 + threadIdx.x;
    s[threadIdx.x] = (i < N_NODES) ? g_cnt[i] : 0;
    __syncthreads();
    for (int off = 128; off > 0; off >>= 1) {
        if (threadIdx.x < off) s[threadIdx.x] += s[threadIdx.x + off];
        __syncthreads();
    }
    if (threadIdx.x == 0) g_bsum[blockIdx.x] = s[0];
}

__global__ void scan2_kernel() {   // scan the 391 block sums (1 block, 512 thr)
    __shared__ int s[512];
    int t = threadIdx.x;
    int v0 = (t < NBLK) ? g_bsum[t] : 0;
    s[t] = v0;
    __syncthreads();
    for (int off = 1; off < 512; off <<= 1) {
        int v = (t >= off) ? s[t - off] : 0;
        __syncthreads();
        s[t] += v;
        __syncthreads();
    }
    if (t < NBLK) g_boff[t] = s[t] - v0;   // exclusive
    if (t == 511) g_rowptr[N_NODES] = N_EDGES;
}

__global__ void scan3_kernel() {   // block-local exclusive scan + offset; zero cnt
    __shared__ int s[256];
    int t = threadIdx.x;
    int i = blockIdx.x * 256 + t;
    int v0 = (i < N_NODES) ? g_cnt[i] : 0;
    s[t] = v0;
    __syncthreads();
    for (int off = 1; off < 256; off <<= 1) {
        int v = (t >= off) ? s[t - off] : 0;
        __syncthreads();
        s[t] += v;
        __syncthreads();
    }
    if (i < N_NODES) {
        int start = g_boff[blockIdx.x] + s[t] - v0;
        g_rowptr[i] = start;
        g_ofs[i]    = start;
        g_cnt[i]    = 0;     // restore invariant for the next call/replay
    }
}

// ---------------------------------------------------------------------------
// Bucket-place edges by dst: es[p] = {src, weight_bits} (fused dtype detect)
// ---------------------------------------------------------------------------
__global__ void sort_kernel(const void* __restrict__ ei,
                            const float* __restrict__ ew) {
    int i = blockIdx.x * blockDim.x + threadIdx.x;
    if (i >= N_EDGES) return;
    bool is64 = warp_is64((const int*)ei, i);
    int src, dst;
    if (is64) {
        src = (int)((const long long*)ei)[i];
        dst = (int)((const long long*)ei)[(long long)N_EDGES + i];
    } else {
        src = ((const int*)ei)[i];
        dst = ((const int*)ei)[N_EDGES + i];
    }
    int p = atomicAdd(&g_ofs[dst], 1);
    g_es[p] = make_int2(src, __float_as_int(ew[i]));
}

// ---------------------------------------------------------------------------
// Gather-aggregate: hsum[n] = h[n] + sum_{e in CSR row n} hHalf[src_e] * w_e
// One warp per node. Lanes 0-15 take even edges, 16-31 odd edges; lane's
// chunk c = lane&15 covers row elements [4c, 4c+4). fp16 rows (128B), fp32 acc.
// ---------------------------------------------------------------------------
__device__ __forceinline__ void fma_row(float4& acc, uint2 r, float w) {
    __half2 h01 = *reinterpret_cast<__half2*>(&r.x);
    __half2 h23 = *reinterpret_cast<__half2*>(&r.y);
    float2 f01 = __half22float2(h01);
    float2 f23 = __half22float2(h23);
    acc.x += f01.x * w; acc.y += f01.y * w;
    acc.z += f23.x * w; acc.w += f23.y * w;
}

__global__ __launch_bounds__(256)
void gather_kernel(const float* __restrict__ h, float* __restrict__ hsum) {
    int gwarp = (blockIdx.x * 256 + threadIdx.x) >> 5;
    if (gwarp >= N_NODES) return;
    int lane = threadIdx.x & 31;
    int half = lane >> 4;
    int c    = lane & 15;
    int n    = gwarp;

    int beg = g_rowptr[n];
    int end = g_rowptr[n + 1];

    const uint2* hh = (const uint2*)g_hHalf;   // 16 uint2 per row

    float4 a0 = make_float4(0.f, 0.f, 0.f, 0.f);
    float4 a1 = make_float4(0.f, 0.f, 0.f, 0.f);
    float4 a2 = make_float4(0.f, 0.f, 0.f, 0.f);
    float4 a3 = make_float4(0.f, 0.f, 0.f, 0.f);

    int e = beg + half;   // this half's edges: e, e+2, e+4, ...
    // 8-deep unroll per half: 16 edges in flight per warp
    for (; e + 14 < end; e += 16) {
        int2 m0 = g_es[e];      int2 m1 = g_es[e + 2];
        int2 m2 = g_es[e + 4];  int2 m3 = g_es[e + 6];
        int2 m4 = g_es[e + 8];  int2 m5 = g_es[e + 10];
        int2 m6 = g_es[e + 12]; int2 m7 = g_es[e + 14];
        uint2 r0 = hh[(size_t)m0.x * 16 + c];
        uint2 r1 = hh[(size_t)m1.x * 16 + c];
        uint2 r2 = hh[(size_t)m2.x * 16 + c];
        uint2 r3 = hh[(size_t)m3.x * 16 + c];
        uint2 r4 = hh[(size_t)m4.x * 16 + c];
        uint2 r5 = hh[(size_t)m5.x * 16 + c];
        uint2 r6 = hh[(size_t)m6.x * 16 + c];
        uint2 r7 = hh[(size_t)m7.x * 16 + c];
        fma_row(a0, r0, __int_as_float(m0.y));
        fma_row(a1, r1, __int_as_float(m1.y));
        fma_row(a2, r2, __int_as_float(m2.y));
        fma_row(a3, r3, __int_as_float(m3.y));
        fma_row(a0, r4, __int_as_float(m4.y));
        fma_row(a1, r5, __int_as_float(m5.y));
        fma_row(a2, r6, __int_as_float(m6.y));
        fma_row(a3, r7, __int_as_float(m7.y));
    }
    for (; e < end; e += 2) {
        int2 m = g_es[e];
        uint2 r = hh[(size_t)m.x * 16 + c];
        fma_row(a0, r, __int_as_float(m.y));
    }

    a0.x += a1.x + a2.x + a3.x;
    a0.y += a1.y + a2.y + a3.y;
    a0.z += a1.z + a2.z + a3.z;
    a0.w += a1.w + a2.w + a3.w;

    // combine halves: lane += lane+16
    a0.x += __shfl_down_sync(0xffffffffu, a0.x, 16);
    a0.y += __shfl_down_sync(0xffffffffu, a0.y, 16);
    a0.z += __shfl_down_sync(0xffffffffu, a0.z, 16);
    a0.w += __shfl_down_sync(0xffffffffu, a0.w, 16);

    if (half == 0) {
        float4 hv = ((const float4*)h)[(size_t)n * 16 + c];
        a0.x += hv.x; a0.y += hv.y; a0.z += hv.z; a0.w += hv.w;
        ((float4*)hsum)[(size_t)n * 16 + c] = a0;
    }
}

// ---------------------------------------------------------------------------
// Dense GEMM: out[n,:NC] = act( in[n] @ W[K,NC] + b ), W in smem.
// Optionally also emits fp16 copy of the output row (for the gather path).
// ---------------------------------------------------------------------------
template<int K, int NC, bool RELU, bool WRITE_HALF>
__global__ __launch_bounds__(256)
void gemm_kernel(const float* __restrict__ in,
                 const float* __restrict__ W, const float* __restrict__ b,
                 float* __restrict__ out) {
    constexpr int TPN    = NC / 4;
    constexpr int GROUPS = 256 / TPN;
    constexpr int NPB    = 64;

    __shared__ __align__(16) float Ws[K * NC];
    __shared__ __align__(16) float bs[NC];

    int tid = threadIdx.x;
    for (int i = tid; i < K * NC / 4; i += 256)
        ((float4*)Ws)[i] = ((const float4*)W)[i];
    if (tid < NC) bs[tid] = b[tid];
    __syncthreads();

    int cg    = tid % TPN;
    int grp   = tid / TPN;
    int node0 = blockIdx.x * NPB;

    for (int n = node0 + grp; n < node0 + NPB && n < N_NODES; n += GROUPS) {
        const float4* row = (const float4*)(in + (size_t)n * K);
        float4 acc = ((const float4*)bs)[cg];

        #pragma unroll
        for (int k4 = 0; k4 < K / 4; k4++) {
            float4 xv = row[k4];
            const float4* wr = (const float4*)Ws + (k4 * 4) * TPN + cg;
            float4 w0 = wr[0 * TPN];
            float4 w1 = wr[1 * TPN];
            float4 w2 = wr[2 * TPN];
            float4 w3 = wr[3 * TPN];
            acc.x += xv.x * w0.x + xv.y * w1.x + xv.z * w2.x + xv.w * w3.x;
            acc.y += xv.x * w0.y + xv.y * w1.y + xv.z * w2.y + xv.w * w3.y;
            acc.z += xv.x * w0.z + xv.y * w1.z + xv.z * w2.z + xv.w * w3.z;
            acc.w += xv.x * w0.w + xv.y * w1.w + xv.z * w2.w + xv.w * w3.w;
        }
        if (RELU) {
            acc.x = fmaxf(acc.x, 0.f);
            acc.y = fmaxf(acc.y, 0.f);
            acc.z = fmaxf(acc.z, 0.f);
            acc.w = fmaxf(acc.w, 0.f);
        }
        ((float4*)(out + (size_t)n * NC))[cg] = acc;
        if (WRITE_HALF) {
            uint2 hp;
            __half2 p01 = __floats2half2_rn(acc.x, acc.y);
            __half2 p23 = __floats2half2_rn(acc.z, acc.w);
            hp.x = *reinterpret_cast<unsigned*>(&p01);
            hp.y = *reinterpret_cast<unsigned*>(&p23);
            ((uint2*)g_hHalf)[(size_t)n * TPN + cg] = hp;
        }
    }
}

// ---------------------------------------------------------------------------
// Launch
// ---------------------------------------------------------------------------
extern "C" void kernel_launch(void* const* d_in, const int* in_sizes, int n_in,
                              void* d_out, int out_size) {
    const float* x     = (const float*)d_in[0];
    const void*  ei    = d_in[1];
    const float* ew    = (const float*)d_in[2];
    const float* W_in  = (const float*)d_in[3];
    const float* b_in  = (const float*)d_in[4];
    const float* W_g   = (const float*)d_in[5];
    const float* b_g   = (const float*)d_in[6];
    const float* W_out = (const float*)d_in[7];
    const float* b_out = (const float*)d_in[8];
    float*       out   = (float*)d_out;

    float *hA, *hB, *hsum;
    cudaGetSymbolAddress((void**)&hA,   g_hA);
    cudaGetSymbolAddress((void**)&hB,   g_hB);
    cudaGetSymbolAddress((void**)&hsum, g_hsum);

    const int node_blocks   = (N_NODES + 63) / 64;
    const int edge_blocks   = (N_EDGES + 255) / 256;
    const int gather_blocks = (N_NODES + 7) / 8;     // 1 warp per node, 8/block

    // CSR build; gemm_in is independent and slotted 4th (ncu capture slot)
    hist_kernel<<<edge_blocks, 256>>>(ei);
    scan1_kernel<<<NBLK, 256>>>();
    scan2_kernel<<<1, 512>>>();
    gemm_kernel<IN_DIM, HID, false, true><<<node_blocks, 256>>>(x, W_in, b_in, hA);
    scan3_kernel<<<NBLK, 256>>>();
    sort_kernel<<<edge_blocks, 256>>>(ei, ew);

    float* cur = hA;
    float* nxt = hB;
    for (int l = 0; l < N_LAYERS; l++) {
        gather_kernel<<<gather_blocks, 256>>>(cur, hsum);
        bool last = (l == N_LAYERS - 1);
        if (!last)
            gemm_kernel<HID, HID, true, true><<<node_blocks, 256>>>(
                hsum, W_g + (size_t)l * HID * HID, b_g + (size_t)l * HID, nxt);
        else
            gemm_kernel<HID, HID, true, false><<<node_blocks, 256>>>(
                hsum, W_g + (size_t)l * HID * HID, b_g + (size_t)l * HID, nxt);
        float* t = cur; cur = nxt; nxt = t;
    }

    gemm_kernel<HID, OUT_DIM, false, false><<<node_blocks, 256>>>(
        cur, W_out, b_out, out);
}

// round 6
// speedup vs baseline: 1.6988x; 1.6988x over previous
#include <cuda_runtime.h>
#include <cuda_fp16.h>

#define N_NODES 100000
#define N_EDGES 3200000
#define IN_DIM 128
#define HID 64
#define OUT_DIM 32
#define N_LAYERS 3

#define NBLK ((N_NODES + 255) / 256)   // 391 scan blocks

// Scratch: device globals (alloc-free, graph-capture safe; zero-init at load)
__device__ float  g_hA[N_NODES * HID];
__device__ float  g_hB[N_NODES * HID];
__device__ float  g_hsum[N_NODES * HID];
__device__ __half g_hHalf[N_NODES * HID];   // fp16 copy of current h for gather
__device__ int2   g_es[N_EDGES];            // {src, weight_bits} grouped by dst
__device__ int    g_cnt[N_NODES];           // left zeroed at end of every call
__device__ int    g_rowptr[N_NODES + 1];
__device__ int    g_ofs[N_NODES];
__device__ int    g_bsum[NBLK];
__device__ int    g_boff[NBLK];

// ---------------------------------------------------------------------------
// Per-warp dtype detect: int64 elements (values < 2^31) have zero odd words.
// ---------------------------------------------------------------------------
__device__ __forceinline__ bool warp_is64(const int* ei32, int i) {
    return __all_sync(0xffffffffu, ei32[2 * i + 1] == 0);
}

// ---------------------------------------------------------------------------
// Histogram of dst (fused dtype detect). g_cnt must enter zeroed.
// ---------------------------------------------------------------------------
__global__ void hist_kernel(const void* __restrict__ ei) {
    int i = blockIdx.x * blockDim.x + threadIdx.x;
    if (i >= N_EDGES) return;
    bool is64 = warp_is64((const int*)ei, i);
    int dst = is64 ? (int)((const long long*)ei)[(long long)N_EDGES + i]
                   : ((const int*)ei)[N_EDGES + i];
    atomicAdd(&g_cnt[dst], 1);
}

// ---------------------------------------------------------------------------
// 3-phase exclusive scan of g_cnt -> g_rowptr / g_ofs
// ---------------------------------------------------------------------------
__global__ void scan1_kernel() {
    __shared__ int s[256];
    int i = blockIdx.x * 256 + threadIdx.x;
    s[threadIdx.x] = (i < N_NODES) ? g_cnt[i] : 0;
    __syncthreads();
    for (int off = 128; off > 0; off >>= 1) {
        if (threadIdx.x < off) s[threadIdx.x] += s[threadIdx.x + off];
        __syncthreads();
    }
    if (threadIdx.x == 0) g_bsum[blockIdx.x] = s[0];
}

__global__ void scan2_kernel() {
    __shared__ int s[512];
    int t = threadIdx.x;
    int v0 = (t < NBLK) ? g_bsum[t] : 0;
    s[t] = v0;
    __syncthreads();
    for (int off = 1; off < 512; off <<= 1) {
        int v = (t >= off) ? s[t - off] : 0;
        __syncthreads();
        s[t] += v;
        __syncthreads();
    }
    if (t < NBLK) g_boff[t] = s[t] - v0;   // exclusive
    if (t == 511) g_rowptr[N_NODES] = N_EDGES;
}

__global__ void scan3_kernel() {
    __shared__ int s[256];
    int t = threadIdx.x;
    int i = blockIdx.x * 256 + t;
    int v0 = (i < N_NODES) ? g_cnt[i] : 0;
    s[t] = v0;
    __syncthreads();
    for (int off = 1; off < 256; off <<= 1) {
        int v = (t >= off) ? s[t - off] : 0;
        __syncthreads();
        s[t] += v;
        __syncthreads();
    }
    if (i < N_NODES) {
        int start = g_boff[blockIdx.x] + s[t] - v0;
        g_rowptr[i] = start;
        g_ofs[i]    = start;
        g_cnt[i]    = 0;     // restore invariant for the next call/replay
    }
}

// ---------------------------------------------------------------------------
// Bucket-place edges by dst: es[p] = {src, weight_bits}
// ---------------------------------------------------------------------------
__global__ void sort_kernel(const void* __restrict__ ei,
                            const float* __restrict__ ew) {
    int i = blockIdx.x * blockDim.x + threadIdx.x;
    if (i >= N_EDGES) return;
    bool is64 = warp_is64((const int*)ei, i);
    int src, dst;
    if (is64) {
        src = (int)((const long long*)ei)[i];
        dst = (int)((const long long*)ei)[(long long)N_EDGES + i];
    } else {
        src = ((const int*)ei)[i];
        dst = ((const int*)ei)[N_EDGES + i];
    }
    int p = atomicAdd(&g_ofs[dst], 1);
    g_es[p] = make_int2(src, __float_as_int(ew[i]));
}

// ---------------------------------------------------------------------------
// Gather-aggregate: hsum[n] = h[n] + sum_{e in CSR row n} hHalf[src_e] * w_e
// One warp per node; halves of the warp take even/odd edges; 8-deep unroll.
// ---------------------------------------------------------------------------
__device__ __forceinline__ void fma_row(float4& acc, uint2 r, float w) {
    __half2 h01 = *reinterpret_cast<__half2*>(&r.x);
    __half2 h23 = *reinterpret_cast<__half2*>(&r.y);
    float2 f01 = __half22float2(h01);
    float2 f23 = __half22float2(h23);
    acc.x += f01.x * w; acc.y += f01.y * w;
    acc.z += f23.x * w; acc.w += f23.y * w;
}

__global__ __launch_bounds__(256)
void gather_kernel(const float* __restrict__ h, float* __restrict__ hsum) {
    int gwarp = (blockIdx.x * 256 + threadIdx.x) >> 5;
    if (gwarp >= N_NODES) return;
    int lane = threadIdx.x & 31;
    int half = lane >> 4;
    int c    = lane & 15;
    int n    = gwarp;

    int beg = g_rowptr[n];
    int end = g_rowptr[n + 1];

    const uint2* hh = (const uint2*)g_hHalf;   // 16 uint2 per row

    float4 a0 = make_float4(0.f, 0.f, 0.f, 0.f);
    float4 a1 = make_float4(0.f, 0.f, 0.f, 0.f);
    float4 a2 = make_float4(0.f, 0.f, 0.f, 0.f);
    float4 a3 = make_float4(0.f, 0.f, 0.f, 0.f);

    int e = beg + half;
    for (; e + 14 < end; e += 16) {
        int2 m0 = g_es[e];      int2 m1 = g_es[e + 2];
        int2 m2 = g_es[e + 4];  int2 m3 = g_es[e + 6];
        int2 m4 = g_es[e + 8];  int2 m5 = g_es[e + 10];
        int2 m6 = g_es[e + 12]; int2 m7 = g_es[e + 14];
        uint2 r0 = hh[(size_t)m0.x * 16 + c];
        uint2 r1 = hh[(size_t)m1.x * 16 + c];
        uint2 r2 = hh[(size_t)m2.x * 16 + c];
        uint2 r3 = hh[(size_t)m3.x * 16 + c];
        uint2 r4 = hh[(size_t)m4.x * 16 + c];
        uint2 r5 = hh[(size_t)m5.x * 16 + c];
        uint2 r6 = hh[(size_t)m6.x * 16 + c];
        uint2 r7 = hh[(size_t)m7.x * 16 + c];
        fma_row(a0, r0, __int_as_float(m0.y));
        fma_row(a1, r1, __int_as_float(m1.y));
        fma_row(a2, r2, __int_as_float(m2.y));
        fma_row(a3, r3, __int_as_float(m3.y));
        fma_row(a0, r4, __int_as_float(m4.y));
        fma_row(a1, r5, __int_as_float(m5.y));
        fma_row(a2, r6, __int_as_float(m6.y));
        fma_row(a3, r7, __int_as_float(m7.y));
    }
    for (; e < end; e += 2) {
        int2 m = g_es[e];
        uint2 r = hh[(size_t)m.x * 16 + c];
        fma_row(a0, r, __int_as_float(m.y));
    }

    a0.x += a1.x + a2.x + a3.x;
    a0.y += a1.y + a2.y + a3.y;
    a0.z += a1.z + a2.z + a3.z;
    a0.w += a1.w + a2.w + a3.w;

    a0.x += __shfl_down_sync(0xffffffffu, a0.x, 16);
    a0.y += __shfl_down_sync(0xffffffffu, a0.y, 16);
    a0.z += __shfl_down_sync(0xffffffffu, a0.z, 16);
    a0.w += __shfl_down_sync(0xffffffffu, a0.w, 16);

    if (half == 0) {
        float4 hv = ((const float4*)h)[(size_t)n * 16 + c];
        a0.x += hv.x; a0.y += hv.y; a0.z += hv.z; a0.w += hv.w;
        ((float4*)hsum)[(size_t)n * 16 + c] = a0;
    }
}

// ---------------------------------------------------------------------------
// Dense GEMM: out[n,:NC] = act( in[n] @ W[K,NC] + b ), W in smem.
// NOTE: unroll capped at 4 — full unroll overflows the RF and spills to
// DRAM-backed local memory (round-4 profile: 128 regs, 2.4GB spill traffic).
// ---------------------------------------------------------------------------
template<int K, int NC, bool RELU, bool WRITE_HALF>
__global__ __launch_bounds__(256)
void gemm_kernel(const float* __restrict__ in,
                 const float* __restrict__ W, const float* __restrict__ b,
                 float* __restrict__ out) {
    constexpr int TPN    = NC / 4;
    constexpr int GROUPS = 256 / TPN;
    constexpr int NPB    = 64;

    __shared__ __align__(16) float Ws[K * NC];
    __shared__ __align__(16) float bs[NC];

    int tid = threadIdx.x;
    for (int i = tid; i < K * NC / 4; i += 256)
        ((float4*)Ws)[i] = ((const float4*)W)[i];
    if (tid < NC) bs[tid] = b[tid];
    __syncthreads();

    int cg    = tid % TPN;
    int grp   = tid / TPN;
    int node0 = blockIdx.x * NPB;

    for (int n = node0 + grp; n < node0 + NPB && n < N_NODES; n += GROUPS) {
        const float4* row = (const float4*)(in + (size_t)n * K);
        float4 acc = ((const float4*)bs)[cg];

        #pragma unroll 4
        for (int k4 = 0; k4 < K / 4; k4++) {
            float4 xv = row[k4];
            const float4* wr = (const float4*)Ws + (k4 * 4) * TPN + cg;
            float4 w0 = wr[0 * TPN];
            float4 w1 = wr[1 * TPN];
            float4 w2 = wr[2 * TPN];
            float4 w3 = wr[3 * TPN];
            acc.x += xv.x * w0.x + xv.y * w1.x + xv.z * w2.x + xv.w * w3.x;
            acc.y += xv.x * w0.y + xv.y * w1.y + xv.z * w2.y + xv.w * w3.y;
            acc.z += xv.x * w0.z + xv.y * w1.z + xv.z * w2.z + xv.w * w3.z;
            acc.w += xv.x * w0.w + xv.y * w1.w + xv.z * w2.w + xv.w * w3.w;
        }
        if (RELU) {
            acc.x = fmaxf(acc.x, 0.f);
            acc.y = fmaxf(acc.y, 0.f);
            acc.z = fmaxf(acc.z, 0.f);
            acc.w = fmaxf(acc.w, 0.f);
        }
        ((float4*)(out + (size_t)n * NC))[cg] = acc;
        if (WRITE_HALF) {
            uint2 hp;
            __half2 p01 = __floats2half2_rn(acc.x, acc.y);
            __half2 p23 = __floats2half2_rn(acc.z, acc.w);
            hp.x = *reinterpret_cast<unsigned*>(&p01);
            hp.y = *reinterpret_cast<unsigned*>(&p23);
            ((uint2*)g_hHalf)[(size_t)n * TPN + cg] = hp;
        }
    }
}

// ---------------------------------------------------------------------------
// Launch
// ---------------------------------------------------------------------------
extern "C" void kernel_launch(void* const* d_in, const int* in_sizes, int n_in,
                              void* d_out, int out_size) {
    const float* x     = (const float*)d_in[0];
    const void*  ei    = d_in[1];
    const float* ew    = (const float*)d_in[2];
    const float* W_in  = (const float*)d_in[3];
    const float* b_in  = (const float*)d_in[4];
    const float* W_g   = (const float*)d_in[5];
    const float* b_g   = (const float*)d_in[6];
    const float* W_out = (const float*)d_in[7];
    const float* b_out = (const float*)d_in[8];
    float*       out   = (float*)d_out;

    float *hA, *hB, *hsum;
    cudaGetSymbolAddress((void**)&hA,   g_hA);
    cudaGetSymbolAddress((void**)&hB,   g_hB);
    cudaGetSymbolAddress((void**)&hsum, g_hsum);

    const int node_blocks   = (N_NODES + 63) / 64;
    const int edge_blocks   = (N_EDGES + 255) / 256;
    const int gather_blocks = (N_NODES + 7) / 8;     // 1 warp per node

    // CSR build; gemm_in kept at capture slot #4 to verify the spill fix
    hist_kernel<<<edge_blocks, 256>>>(ei);
    scan1_kernel<<<NBLK, 256>>>();
    scan2_kernel<<<1, 512>>>();
    gemm_kernel<IN_DIM, HID, false, true><<<node_blocks, 256>>>(x, W_in, b_in, hA);
    scan3_kernel<<<NBLK, 256>>>();
    sort_kernel<<<edge_blocks, 256>>>(ei, ew);

    float* cur = hA;
    float* nxt = hB;
    for (int l = 0; l < N_LAYERS; l++) {
        gather_kernel<<<gather_blocks, 256>>>(cur, hsum);
        bool last = (l == N_LAYERS - 1);
        if (!last)
            gemm_kernel<HID, HID, true, true><<<node_blocks, 256>>>(
                hsum, W_g + (size_t)l * HID * HID, b_g + (size_t)l * HID, nxt);
        else
            gemm_kernel<HID, HID, true, false><<<node_blocks, 256>>>(
                hsum, W_g + (size_t)l * HID * HID, b_g + (size_t)l * HID, nxt);
        float* t = cur; cur = nxt; nxt = t;
    }

    gemm_kernel<HID, OUT_DIM, false, false><<<node_blocks, 256>>>(
        cur, W_out, b_out, out);
}

// round 7
// speedup vs baseline: 2.4821x; 1.4611x over previous
#include <cuda_runtime.h>
#include <cuda_fp16.h>

#define N_NODES 100000
#define N_EDGES 3200000
#define IN_DIM 128
#define HID 64
#define OUT_DIM 32
#define N_LAYERS 3

#define NBLK ((N_NODES + 255) / 256)   // 391 scan blocks

// Scratch: device globals (alloc-free, graph-capture safe; zero-init at load)
__device__ float  g_hA[N_NODES * HID];
__device__ float  g_hB[N_NODES * HID];
__device__ float  g_hsum[N_NODES * HID];
__device__ __half g_hHalf[N_NODES * HID];   // fp16 copy of current h for gather
__device__ int2   g_es[N_EDGES];            // {src, weight_bits} grouped by dst
__device__ int    g_cnt[N_NODES];           // left zeroed at end of every call
__device__ int    g_rowptr[N_NODES + 1];
__device__ int    g_ofs[N_NODES];
__device__ int    g_bsum[NBLK];
__device__ int    g_boff[NBLK];

// ---------------------------------------------------------------------------
// Per-warp dtype detect: int64 elements (values < 2^31) have zero odd words.
// ---------------------------------------------------------------------------
__device__ __forceinline__ bool warp_is64(const int* ei32, int i) {
    return __all_sync(0xffffffffu, ei32[2 * i + 1] == 0);
}

// ---------------------------------------------------------------------------
// Histogram of dst (fused dtype detect). g_cnt must enter zeroed.
// ---------------------------------------------------------------------------
__global__ void hist_kernel(const void* __restrict__ ei) {
    int i = blockIdx.x * blockDim.x + threadIdx.x;
    if (i >= N_EDGES) return;
    bool is64 = warp_is64((const int*)ei, i);
    int dst = is64 ? (int)((const long long*)ei)[(long long)N_EDGES + i]
                   : ((const int*)ei)[N_EDGES + i];
    atomicAdd(&g_cnt[dst], 1);
}

// ---------------------------------------------------------------------------
// 3-phase exclusive scan of g_cnt -> g_rowptr / g_ofs
// ---------------------------------------------------------------------------
__global__ void scan1_kernel() {
    __shared__ int s[256];
    int i = blockIdx.x * 256 + threadIdx.x;
    s[threadIdx.x] = (i < N_NODES) ? g_cnt[i] : 0;
    __syncthreads();
    for (int off = 128; off > 0; off >>= 1) {
        if (threadIdx.x < off) s[threadIdx.x] += s[threadIdx.x + off];
        __syncthreads();
    }
    if (threadIdx.x == 0) g_bsum[blockIdx.x] = s[0];
}

__global__ void scan2_kernel() {
    __shared__ int s[512];
    int t = threadIdx.x;
    int v0 = (t < NBLK) ? g_bsum[t] : 0;
    s[t] = v0;
    __syncthreads();
    for (int off = 1; off < 512; off <<= 1) {
        int v = (t >= off) ? s[t - off] : 0;
        __syncthreads();
        s[t] += v;
        __syncthreads();
    }
    if (t < NBLK) g_boff[t] = s[t] - v0;   // exclusive
    if (t == 511) g_rowptr[N_NODES] = N_EDGES;
}

__global__ void scan3_kernel() {
    __shared__ int s[256];
    int t = threadIdx.x;
    int i = blockIdx.x * 256 + t;
    int v0 = (i < N_NODES) ? g_cnt[i] : 0;
    s[t] = v0;
    __syncthreads();
    for (int off = 1; off < 256; off <<= 1) {
        int v = (t >= off) ? s[t - off] : 0;
        __syncthreads();
        s[t] += v;
        __syncthreads();
    }
    if (i < N_NODES) {
        int start = g_boff[blockIdx.x] + s[t] - v0;
        g_rowptr[i] = start;
        g_ofs[i]    = start;
        g_cnt[i]    = 0;     // restore invariant for the next call/replay
    }
}

// ---------------------------------------------------------------------------
// Bucket-place edges by dst: es[p] = {src, weight_bits}
// ---------------------------------------------------------------------------
__global__ void sort_kernel(const void* __restrict__ ei,
                            const float* __restrict__ ew) {
    int i = blockIdx.x * blockDim.x + threadIdx.x;
    if (i >= N_EDGES) return;
    bool is64 = warp_is64((const int*)ei, i);
    int src, dst;
    if (is64) {
        src = (int)((const long long*)ei)[i];
        dst = (int)((const long long*)ei)[(long long)N_EDGES + i];
    } else {
        src = ((const int*)ei)[i];
        dst = ((const int*)ei)[N_EDGES + i];
    }
    int p = atomicAdd(&g_ofs[dst], 1);
    g_es[p] = make_int2(src, __float_as_int(ew[i]));
}

// ---------------------------------------------------------------------------
// Gather-aggregate: hsum[n] = h[n] + sum_{e in CSR row n} hHalf[src_e] * w_e
// One warp per node; halves of the warp take even/odd edges; 8-deep unroll.
// ---------------------------------------------------------------------------
__device__ __forceinline__ void fma_row(float4& acc, uint2 r, float w) {
    __half2 h01 = *reinterpret_cast<__half2*>(&r.x);
    __half2 h23 = *reinterpret_cast<__half2*>(&r.y);
    float2 f01 = __half22float2(h01);
    float2 f23 = __half22float2(h23);
    acc.x += f01.x * w; acc.y += f01.y * w;
    acc.z += f23.x * w; acc.w += f23.y * w;
}

__global__ __launch_bounds__(256)
void gather_kernel(const float* __restrict__ h, float* __restrict__ hsum) {
    int gwarp = (blockIdx.x * 256 + threadIdx.x) >> 5;
    if (gwarp >= N_NODES) return;
    int lane = threadIdx.x & 31;
    int half = lane >> 4;
    int c    = lane & 15;
    int n    = gwarp;

    int beg = g_rowptr[n];
    int end = g_rowptr[n + 1];

    const uint2* hh = (const uint2*)g_hHalf;   // 16 uint2 per row

    float4 a0 = make_float4(0.f, 0.f, 0.f, 0.f);
    float4 a1 = make_float4(0.f, 0.f, 0.f, 0.f);
    float4 a2 = make_float4(0.f, 0.f, 0.f, 0.f);
    float4 a3 = make_float4(0.f, 0.f, 0.f, 0.f);

    int e = beg + half;
    for (; e + 14 < end; e += 16) {
        int2 m0 = g_es[e];      int2 m1 = g_es[e + 2];
        int2 m2 = g_es[e + 4];  int2 m3 = g_es[e + 6];
        int2 m4 = g_es[e + 8];  int2 m5 = g_es[e + 10];
        int2 m6 = g_es[e + 12]; int2 m7 = g_es[e + 14];
        uint2 r0 = hh[(size_t)m0.x * 16 + c];
        uint2 r1 = hh[(size_t)m1.x * 16 + c];
        uint2 r2 = hh[(size_t)m2.x * 16 + c];
        uint2 r3 = hh[(size_t)m3.x * 16 + c];
        uint2 r4 = hh[(size_t)m4.x * 16 + c];
        uint2 r5 = hh[(size_t)m5.x * 16 + c];
        uint2 r6 = hh[(size_t)m6.x * 16 + c];
        uint2 r7 = hh[(size_t)m7.x * 16 + c];
        fma_row(a0, r0, __int_as_float(m0.y));
        fma_row(a1, r1, __int_as_float(m1.y));
        fma_row(a2, r2, __int_as_float(m2.y));
        fma_row(a3, r3, __int_as_float(m3.y));
        fma_row(a0, r4, __int_as_float(m4.y));
        fma_row(a1, r5, __int_as_float(m5.y));
        fma_row(a2, r6, __int_as_float(m6.y));
        fma_row(a3, r7, __int_as_float(m7.y));
    }
    for (; e < end; e += 2) {
        int2 m = g_es[e];
        uint2 r = hh[(size_t)m.x * 16 + c];
        fma_row(a0, r, __int_as_float(m.y));
    }

    a0.x += a1.x + a2.x + a3.x;
    a0.y += a1.y + a2.y + a3.y;
    a0.z += a1.z + a2.z + a3.z;
    a0.w += a1.w + a2.w + a3.w;

    a0.x += __shfl_down_sync(0xffffffffu, a0.x, 16);
    a0.y += __shfl_down_sync(0xffffffffu, a0.y, 16);
    a0.z += __shfl_down_sync(0xffffffffu, a0.z, 16);
    a0.w += __shfl_down_sync(0xffffffffu, a0.w, 16);

    if (half == 0) {
        float4 hv = ((const float4*)h)[(size_t)n * 16 + c];
        a0.x += hv.x; a0.y += hv.y; a0.z += hv.z; a0.w += hv.w;
        ((float4*)hsum)[(size_t)n * 16 + c] = a0;
    }
}

// ---------------------------------------------------------------------------
// Dense GEMM, 4 rows per thread: amortizes each W LDS.128 over 4 nodes
// (1B smem/FMA instead of 4B -> fma-bound, not crossbar-bound).
// Each thread: 4 nodes x 4 columns = 16 fp32 accumulators.
// unroll 2: keeps live set ~64 regs (full unroll spills — round-4 lesson).
// ---------------------------------------------------------------------------
template<int K, int NC, bool RELU, bool WRITE_HALF>
__global__ __launch_bounds__(256)
void gemm_kernel(const float* __restrict__ in,
                 const float* __restrict__ W, const float* __restrict__ b,
                 float* __restrict__ out) {
    constexpr int TPN  = NC / 4;            // threads covering one node's cols
    constexpr int GRPS = 256 / TPN;         // node-groups per block
    constexpr int NPB  = GRPS * 4;          // nodes per block

    __shared__ __align__(16) float Ws[K * NC];
    __shared__ __align__(16) float bs[NC];

    int tid = threadIdx.x;
    for (int i = tid; i < K * NC / 4; i += 256)
        ((float4*)Ws)[i] = ((const float4*)W)[i];
    if (tid < NC) bs[tid] = b[tid];
    __syncthreads();

    int cg = tid % TPN;
    int n0 = blockIdx.x * NPB + (tid / TPN) * 4;
    if (n0 >= N_NODES) return;

    // clamp row pointers for the grid tail (duplicate reads are harmless;
    // stores are predicated)
    int n1 = (n0 + 1 < N_NODES) ? n0 + 1 : n0;
    int n2 = (n0 + 2 < N_NODES) ? n0 + 2 : n0;
    int n3 = (n0 + 3 < N_NODES) ? n0 + 3 : n0;

    const float4* r0 = (const float4*)(in + (size_t)n0 * K);
    const float4* r1 = (const float4*)(in + (size_t)n1 * K);
    const float4* r2 = (const float4*)(in + (size_t)n2 * K);
    const float4* r3 = (const float4*)(in + (size_t)n3 * K);

    float4 bias = ((const float4*)bs)[cg];
    float4 acc0 = bias, acc1 = bias, acc2 = bias, acc3 = bias;

    #pragma unroll 2
    for (int k4 = 0; k4 < K / 4; k4++) {
        const float4* wr = (const float4*)Ws + (k4 * 4) * TPN + cg;
        float4 w0 = wr[0 * TPN];
        float4 w1 = wr[1 * TPN];
        float4 w2 = wr[2 * TPN];
        float4 w3 = wr[3 * TPN];
        float4 xv;

        xv = r0[k4];
        acc0.x += xv.x * w0.x + xv.y * w1.x + xv.z * w2.x + xv.w * w3.x;
        acc0.y += xv.x * w0.y + xv.y * w1.y + xv.z * w2.y + xv.w * w3.y;
        acc0.z += xv.x * w0.z + xv.y * w1.z + xv.z * w2.z + xv.w * w3.z;
        acc0.w += xv.x * w0.w + xv.y * w1.w + xv.z * w2.w + xv.w * w3.w;

        xv = r1[k4];
        acc1.x += xv.x * w0.x + xv.y * w1.x + xv.z * w2.x + xv.w * w3.x;
        acc1.y += xv.x * w0.y + xv.y * w1.y + xv.z * w2.y + xv.w * w3.y;
        acc1.z += xv.x * w0.z + xv.y * w1.z + xv.z * w2.z + xv.w * w3.z;
        acc1.w += xv.x * w0.w + xv.y * w1.w + xv.z * w2.w + xv.w * w3.w;

        xv = r2[k4];
        acc2.x += xv.x * w0.x + xv.y * w1.x + xv.z * w2.x + xv.w * w3.x;
        acc2.y += xv.x * w0.y + xv.y * w1.y + xv.z * w2.y + xv.w * w3.y;
        acc2.z += xv.x * w0.z + xv.y * w1.z + xv.z * w2.z + xv.w * w3.z;
        acc2.w += xv.x * w0.w + xv.y * w1.w + xv.z * w2.w + xv.w * w3.w;

        xv = r3[k4];
        acc3.x += xv.x * w0.x + xv.y * w1.x + xv.z * w2.x + xv.w * w3.x;
        acc3.y += xv.x * w0.y + xv.y * w1.y + xv.z * w2.y + xv.w * w3.y;
        acc3.z += xv.x * w0.z + xv.y * w1.z + xv.z * w2.z + xv.w * w3.z;
        acc3.w += xv.x * w0.w + xv.y * w1.w + xv.z * w2.w + xv.w * w3.w;
    }

    float4 accs[4] = {acc0, acc1, acc2, acc3};
    #pragma unroll
    for (int r = 0; r < 4; r++) {
        int n = n0 + r;
        if (n >= N_NODES) break;
        float4 a = accs[r];
        if (RELU) {
            a.x = fmaxf(a.x, 0.f);
            a.y = fmaxf(a.y, 0.f);
            a.z = fmaxf(a.z, 0.f);
            a.w = fmaxf(a.w, 0.f);
        }
        ((float4*)(out + (size_t)n * NC))[cg] = a;
        if (WRITE_HALF) {
            uint2 hp;
            __half2 p01 = __floats2half2_rn(a.x, a.y);
            __half2 p23 = __floats2half2_rn(a.z, a.w);
            hp.x = *reinterpret_cast<unsigned*>(&p01);
            hp.y = *reinterpret_cast<unsigned*>(&p23);
            ((uint2*)g_hHalf)[(size_t)n * TPN + cg] = hp;
        }
    }
}

// ---------------------------------------------------------------------------
// Launch
// ---------------------------------------------------------------------------
extern "C" void kernel_launch(void* const* d_in, const int* in_sizes, int n_in,
                              void* d_out, int out_size) {
    const float* x     = (const float*)d_in[0];
    const void*  ei    = d_in[1];
    const float* ew    = (const float*)d_in[2];
    const float* W_in  = (const float*)d_in[3];
    const float* b_in  = (const float*)d_in[4];
    const float* W_g   = (const float*)d_in[5];
    const float* b_g   = (const float*)d_in[6];
    const float* W_out = (const float*)d_in[7];
    const float* b_out = (const float*)d_in[8];
    float*       out   = (float*)d_out;

    float *hA, *hB, *hsum;
    cudaGetSymbolAddress((void**)&hA,   g_hA);
    cudaGetSymbolAddress((void**)&hB,   g_hB);
    cudaGetSymbolAddress((void**)&hsum, g_hsum);

    const int edge_blocks   = (N_EDGES + 255) / 256;
    const int gather_blocks = (N_NODES + 7) / 8;     // 1 warp per node

    // nodes per block: NC=64 -> 64/block; NC=32 -> 128/block
    const int gemm64_blocks = (N_NODES + 63) / 64;
    const int gemm32_blocks = (N_NODES + 127) / 128;

    // CSR build; gemm_in kept at capture slot #4 to profile the smem fix
    hist_kernel<<<edge_blocks, 256>>>(ei);
    scan1_kernel<<<NBLK, 256>>>();
    scan2_kernel<<<1, 512>>>();
    gemm_kernel<IN_DIM, HID, false, true><<<gemm64_blocks, 256>>>(x, W_in, b_in, hA);
    scan3_kernel<<<NBLK, 256>>>();
    sort_kernel<<<edge_blocks, 256>>>(ei, ew);

    float* cur = hA;
    float* nxt = hB;
    for (int l = 0; l < N_LAYERS; l++) {
        gather_kernel<<<gather_blocks, 256>>>(cur, hsum);
        bool last = (l == N_LAYERS - 1);
        if (!last)
            gemm_kernel<HID, HID, true, true><<<gemm64_blocks, 256>>>(
                hsum, W_g + (size_t)l * HID * HID, b_g + (size_t)l * HID, nxt);
        else
            gemm_kernel<HID, HID, true, false><<<gemm64_blocks, 256>>>(
                hsum, W_g + (size_t)l * HID * HID, b_g + (size_t)l * HID, nxt);
        float* t = cur; cur = nxt; nxt = t;
    }

    gemm_kernel<HID, OUT_DIM, false, false><<<gemm32_blocks, 256>>>(
        cur, W_out, b_out, out);
}